// round 14
// baseline (speedup 1.0000x reference)
#include <cuda_runtime.h>
#include <cuda_bf16.h>
#include <cuda_fp16.h>
#include <cstdint>

#define N_NODES  200000
#define N_EDGES  200000
#define N_GRAPHS 128
#define IN_F     256
#define HID_F    128
#define OUT_F    128

// ---------------- scratch (static device globals; no allocation) -------------
__device__ __half g_H1[(size_t)N_NODES * HID_F];  // x @ W1            (fp16)
__device__ float  g_A1[(size_t)N_NODES * HID_F];  // conv1 output (x2)
__device__ __half g_H2[(size_t)N_NODES * HID_F];  // relu(A1)@W2a + R  (fp16)
__device__ float  g_O [(size_t)N_NODES * HID_F];  // conv2 pre-relu
__device__ float g_deg [N_NODES];
__device__ float g_dinv[N_NODES];
__device__ float g_R   [N_GRAPHS * HID_F];        // relu(x[root]) @ W2[128:384]
__device__ float g_gsum[N_GRAPHS * HID_F];
__device__ float g_gcnt[N_GRAPHS];
// transposed fp16 hi/lo weights: Wt[n*K + k]  (2-term split: B = Bh + Bl)
__device__ __half g_Wt1h[HID_F * IN_F];
__device__ __half g_Wt1l[HID_F * IN_F];
__device__ __half g_Wt2h[HID_F * HID_F];
__device__ __half g_Wt2l[HID_F * HID_F];

// ---------------- helpers -----------------------------------------------------
__device__ __forceinline__ void mma_f16(float* c, const uint32_t* a, const uint32_t* b) {
    asm volatile(
        "mma.sync.aligned.m16n8k16.row.col.f32.f16.f16.f32 "
        "{%0,%1,%2,%3}, {%4,%5,%6,%7}, {%8,%9}, {%0,%1,%2,%3};"
        : "+f"(c[0]), "+f"(c[1]), "+f"(c[2]), "+f"(c[3])
        : "r"(a[0]), "r"(a[1]), "r"(a[2]), "r"(a[3]), "r"(b[0]), "r"(b[1]));
}

__device__ __forceinline__ void red_v4(float* addr, float a, float b, float c, float d) {
    asm volatile("red.global.add.v4.f32 [%0], {%1, %2, %3, %4};"
        :: "l"(addr), "f"(a), "f"(b), "f"(c), "f"(d) : "memory");
}

__device__ __forceinline__ uint32_t smem_u32(const void* p) {
    uint32_t a;
    asm("{ .reg .u64 t; cvta.to.shared.u64 t, %1; cvt.u32.u64 %0, t; }"
        : "=r"(a) : "l"(p));
    return a;
}

__device__ __forceinline__ uint32_t h2bits(__half2 h) {
    return *reinterpret_cast<uint32_t*>(&h);
}

// ---------------- fused init + weight prep ------------------------------------
__global__ void k_initprep(const float* __restrict__ W1, const float* __restrict__ W2) {
    if (blockIdx.x < HID_F) {
        int n = blockIdx.x;      // 0..127
        int k = threadIdx.x;     // 0..255
        float v = W1[(size_t)k * HID_F + n];
        __half h = __float2half_rn(v);
        g_Wt1h[n * IN_F + k] = h;
        g_Wt1l[n * IN_F + k] = __float2half_rn(v - __half2float(h));
        if (k < HID_F) {
            float v2 = W2[(size_t)k * OUT_F + n];
            __half h2 = __float2half_rn(v2);
            g_Wt2h[n * HID_F + k] = h2;
            g_Wt2l[n * HID_F + k] = __float2half_rn(v2 - __half2float(h2));
        }
    } else {
        int i = (blockIdx.x - HID_F) * blockDim.x + threadIdx.x;
        if (i < N_NODES) g_deg[i] = 1.0f;           // self-loop
        if (i < N_GRAPHS * HID_F) g_gsum[i] = 0.0f;
        if (i < N_GRAPHS) g_gcnt[i] = 0.0f;
    }
}

__global__ void k_degree(const int* __restrict__ ei) {
    int e = blockIdx.x * blockDim.x + threadIdx.x;
    if (e >= N_EDGES) return;
    atomicAdd(&g_deg[ei[N_EDGES + e]], 1.0f);
}

__global__ void k_dinv(void) {
    int i = blockIdx.x * blockDim.x + threadIdx.x;
    if (i >= N_NODES) return;
    g_dinv[i] = rsqrtf(g_deg[i]);
}

// one warp per edge: D[dst] += H[src] * dinv[src]*dinv[dst]   (fp16 gather, v4 RED)
__global__ void k_edge(const __half* __restrict__ H, float* __restrict__ D,
                       const int* __restrict__ ei) {
    int e = blockIdx.x * (blockDim.x >> 5) + (threadIdx.x >> 5);
    if (e >= N_EDGES) return;
    int lane = threadIdx.x & 31;
    int s = ei[e], d = ei[N_EDGES + e];
    float c = g_dinv[s] * g_dinv[d];
    uint2 raw = *(const uint2*)(H + (size_t)s * HID_F + lane * 4);
    __half2 h0 = *reinterpret_cast<__half2*>(&raw.x);
    __half2 h1 = *reinterpret_cast<__half2*>(&raw.y);
    float2 f0 = __half22float2(h0);
    float2 f1 = __half22float2(h1);
    float* o = D + (size_t)d * HID_F + lane * 4;
    red_v4(o, f0.x * c, f0.y * c, f1.x * c, f1.y * c);
}

// R[g] = relu(x[root[g]]) @ W2[128:384]
__global__ void k_rootgemm(const float* __restrict__ x,
                           const int* __restrict__ root,
                           const float* __restrict__ W2) {
    __shared__ float xr[IN_F];
    int g = blockIdx.x, t = threadIdx.x;
    int r = root[g];
    xr[t]       = fmaxf(x[(size_t)r * IN_F + t], 0.0f);
    xr[t + 128] = fmaxf(x[(size_t)r * IN_F + t + 128], 0.0f);
    __syncthreads();
    float acc = 0.0f;
#pragma unroll 8
    for (int k = 0; k < IN_F; k++)
        acc += xr[k] * W2[(size_t)(HID_F + k) * OUT_F + t];
    g_R[g * HID_F + t] = acc;
}

// ---------------- tensor-core GEMM: C[M,128] = op(A[M,K]) @ Wt^T --------------
// mma.sync m16n8k16 fp16, 2-term split (A*Bh + A*Bl), fp32 accum.
// 2-stage cp.async pipeline: A lands in smem as fp32 (converted to fp16 in the
// compute phase via F2FP), B lands presplit fp16. Zero-fill OOB via src-size.
// Fused epilogue: H(fp16) = C (+ R[batch]);  D(fp32) = C * dinv^2 + bias.
#define BK      32
#define SAPD_A  36                          // floats per A row (pad 4)
#define SAPD_B  40                          // halves per B row (pad 8)
#define A_STAGE (128 * SAPD_A)              // floats per stage
#define B_STAGE (128 * SAPD_B)              // halves per stage per term
#define TG_SMEM (2 * A_STAGE * 4 + 4 * B_STAGE * 2)   // 36864 + 40960 = 77824 B

template<int K, bool RELU_A, bool ADD_R>
__global__ __launch_bounds__(256, 2)
void k_tgemm(const float* __restrict__ A,
             const __half* __restrict__ Bh,
             const __half* __restrict__ Bl,
             __half* __restrict__ H, float* __restrict__ D,
             const float* __restrict__ bias,
             const int* __restrict__ batch, int M) {
    extern __shared__ char smem[];
    float*    sA = (float*)smem;                          // [2][A_STAGE]
    uint16_t* sB = (uint16_t*)(smem + 2 * A_STAGE * 4);   // [2][2][B_STAGE]

    const int tid  = threadIdx.x;
    const int wid  = tid >> 5;
    const int lane = tid & 31;
    const int g8   = lane >> 2;            // 0..7
    const int t2   = (lane & 3) * 2;       // 0,2,4,6
    const int warp_m = (wid >> 2) * 64;    // 0 or 64
    const int warp_n = (wid & 3) * 32;     // 0..96
    const int blockRow = blockIdx.x * 128;
    constexpr int NC = K / BK;

    float acc[4][4][4];
#pragma unroll
    for (int i = 0; i < 4; i++)
#pragma unroll
        for (int j = 0; j < 4; j++)
#pragma unroll
            for (int q = 0; q < 4; q++) acc[i][j][q] = 0.0f;

    // ---- cp.async issue for chunk c into stage c&1 ----
    auto issue_chunk = [&](int c) {
        const int k0 = c * BK;
        const int s  = c & 1;
        uint32_t abase = smem_u32(sA + s * A_STAGE);
#pragma unroll
        for (int it = 0; it < 4; it++) {
            int linear = tid + it * 256;          // 1024 16B lines
            int row = linear >> 3, seg = linear & 7;
            int gr  = blockRow + row;
            uint32_t dst = abase + (uint32_t)(row * SAPD_A + seg * 4) * 4;
            const float* src = A + (size_t)gr * K + k0 + seg * 4;
            int sz = (gr < M) ? 16 : 0;           // zero-fill OOB rows
            asm volatile("cp.async.cg.shared.global [%0], [%1], 16, %2;"
                         :: "r"(dst), "l"(src), "r"(sz) : "memory");
        }
        uint32_t hbase = smem_u32(sB + (2 * s + 0) * B_STAGE);
        uint32_t lbase = smem_u32(sB + (2 * s + 1) * B_STAGE);
#pragma unroll
        for (int it = 0; it < 2; it++) {
            int linear = tid + it * 256;          // 512 16B lines per term
            int n = linear >> 2, seg = linear & 3;
            uint32_t off = (uint32_t)(n * SAPD_B + seg * 8) * 2;
            size_t gi = (size_t)n * K + k0 + seg * 8;
            asm volatile("cp.async.cg.shared.global [%0], [%1], 16;"
                         :: "r"(hbase + off), "l"(Bh + gi) : "memory");
            asm volatile("cp.async.cg.shared.global [%0], [%1], 16;"
                         :: "r"(lbase + off), "l"(Bl + gi) : "memory");
        }
        asm volatile("cp.async.commit_group;" ::: "memory");
    };

    issue_chunk(0);

    for (int c = 0; c < NC; c++) {
        if (c + 1 < NC) {
            issue_chunk(c + 1);   // into other stage (safe: last read at c-1, synced)
            asm volatile("cp.async.wait_group 1;" ::: "memory");
        } else {
            asm volatile("cp.async.wait_group 0;" ::: "memory");
        }
        __syncthreads();

        const int st = c & 1;
        const float*    cA  = sA + st * A_STAGE;
        const uint16_t* cBh = sB + (2 * st + 0) * B_STAGE;
        const uint16_t* cBl = sB + (2 * st + 1) * B_STAGE;
#pragma unroll
        for (int ks = 0; ks < 2; ks++) {
            const int kk = ks * 16;
            uint32_t ah[4][4], bh[4][2], bl[4][2];
#pragma unroll
            for (int mt = 0; mt < 4; mt++) {
                int r1 = (warp_m + mt * 16 + g8) * SAPD_A + kk + t2;
                int r2 = r1 + 8 * SAPD_A;
                float2 x0 = *(const float2*)&cA[r1];
                float2 x1 = *(const float2*)&cA[r2];
                float2 x2 = *(const float2*)&cA[r1 + 8];
                float2 x3 = *(const float2*)&cA[r2 + 8];
                if (RELU_A) {
                    x0.x = fmaxf(x0.x, 0.f); x0.y = fmaxf(x0.y, 0.f);
                    x1.x = fmaxf(x1.x, 0.f); x1.y = fmaxf(x1.y, 0.f);
                    x2.x = fmaxf(x2.x, 0.f); x2.y = fmaxf(x2.y, 0.f);
                    x3.x = fmaxf(x3.x, 0.f); x3.y = fmaxf(x3.y, 0.f);
                }
                ah[mt][0] = h2bits(__floats2half2_rn(x0.x, x0.y));
                ah[mt][1] = h2bits(__floats2half2_rn(x1.x, x1.y));
                ah[mt][2] = h2bits(__floats2half2_rn(x2.x, x2.y));
                ah[mt][3] = h2bits(__floats2half2_rn(x3.x, x3.y));
            }
#pragma unroll
            for (int nt = 0; nt < 4; nt++) {
                int n = warp_n + nt * 8 + g8;
                int ho = n * SAPD_B + kk + t2;
                bh[nt][0] = *(const uint32_t*)&cBh[ho];
                bh[nt][1] = *(const uint32_t*)&cBh[ho + 8];
                bl[nt][0] = *(const uint32_t*)&cBl[ho];
                bl[nt][1] = *(const uint32_t*)&cBl[ho + 8];
            }
#pragma unroll
            for (int mt = 0; mt < 4; mt++)
#pragma unroll
                for (int nt = 0; nt < 4; nt++) {
                    mma_f16(acc[mt][nt], ah[mt], bh[nt]);
                    mma_f16(acc[mt][nt], ah[mt], bl[nt]);
                }
        }
        __syncthreads();   // all warps done reading stage before it is reissued
    }

    // ---- epilogue: H(fp16) = acc (+R[batch]);  D = H*dinv^2 + bias ----
#pragma unroll
    for (int mt = 0; mt < 4; mt++) {
#pragma unroll
        for (int half = 0; half < 2; half++) {
            int row = blockRow + warp_m + mt * 16 + g8 + half * 8;
            if (row >= M) continue;
            float dv = g_dinv[row];
            float ds = dv * dv;
            const float* Rrow = ADD_R ? (g_R + (size_t)batch[row] * HID_F) : nullptr;
#pragma unroll
            for (int nt = 0; nt < 4; nt++) {
                int col = warp_n + nt * 8 + t2;
                float v0 = acc[mt][nt][half * 2 + 0];
                float v1 = acc[mt][nt][half * 2 + 1];
                if (ADD_R) { v0 += Rrow[col]; v1 += Rrow[col + 1]; }
                *(__half2*)(H + (size_t)row * HID_F + col) = __floats2half2_rn(v0, v1);
                float b0 = bias[col], b1 = bias[col + 1];
                *(float2*)(D + (size_t)row * HID_F + col) =
                    make_float2(v0 * ds + b0, v1 * ds + b1);
            }
        }
    }
}

// ---------------- graph mean reduction (batch is sorted) ----------------------
#define NPB 128
__global__ void k_reduce(const int* __restrict__ batch) {
    int c = threadIdx.x;                      // 0..127 (column)
    int start = blockIdx.x * NPB;
    if (start >= N_NODES) return;
    int end = min(start + NPB, N_NODES);
    int curg = batch[start];
    float acc = 0.0f; int cnt = 0;
    for (int i = start; i < end; i++) {
        int g = batch[i];
        if (g != curg) {
            atomicAdd(&g_gsum[curg * HID_F + c], acc);
            if (c == 0) atomicAdd(&g_gcnt[curg], (float)cnt);
            acc = 0.0f; cnt = 0; curg = g;
        }
        acc += fmaxf(g_O[(size_t)i * HID_F + c], 0.0f);
        cnt++;
    }
    atomicAdd(&g_gsum[curg * HID_F + c], acc);
    if (c == 0) atomicAdd(&g_gcnt[curg], (float)cnt);
}

__global__ void k_final(const int* __restrict__ root, float* __restrict__ out) {
    int g = blockIdx.x, c = threadIdx.x;      // 256 threads
    float cnt = g_gcnt[g];
    float v;
    if (c < HID_F) {
        v = g_gsum[g * HID_F + c] / fmaxf(cnt, 1.0f);
    } else {
        v = (cnt > 0.0f) ? g_A1[(size_t)root[g] * HID_F + (c - HID_F)] : 0.0f;
    }
    out[g * 256 + c] = v;
}

// ---------------- launch ------------------------------------------------------
extern "C" void kernel_launch(void* const* d_in, const int* in_sizes, int n_in,
                              void* d_out, int out_size) {
    const float* x     = (const float*)d_in[0];
    const int*   ei    = (const int*)  d_in[1];
    const int*   batch = (const int*)  d_in[2];
    const int*   root  = (const int*)  d_in[3];
    const float* W1    = (const float*)d_in[4];
    const float* b1    = (const float*)d_in[5];
    const float* W2    = (const float*)d_in[6];
    const float* b2    = (const float*)d_in[7];
    float* out = (float*)d_out;

    float *A1, *O;
    __half *H1, *H2;
    __half *Wt1h, *Wt1l, *Wt2h, *Wt2l;
    cudaGetSymbolAddress((void**)&H1, g_H1);
    cudaGetSymbolAddress((void**)&A1, g_A1);
    cudaGetSymbolAddress((void**)&H2, g_H2);
    cudaGetSymbolAddress((void**)&O,  g_O);
    cudaGetSymbolAddress((void**)&Wt1h, g_Wt1h);
    cudaGetSymbolAddress((void**)&Wt1l, g_Wt1l);
    cudaGetSymbolAddress((void**)&Wt2h, g_Wt2h);
    cudaGetSymbolAddress((void**)&Wt2l, g_Wt2l);

    cudaFuncSetAttribute(k_tgemm<IN_F, false, false>,
                         cudaFuncAttributeMaxDynamicSharedMemorySize, TG_SMEM);
    cudaFuncSetAttribute(k_tgemm<HID_F, true, true>,
                         cudaFuncAttributeMaxDynamicSharedMemorySize, TG_SMEM);

    const int gemm_blocks = (N_NODES + 127) / 128;             // 1563
    const int edge_blocks = (N_EDGES + 7) / 8;                 // 8 edges/block @256thr
    const int init_blocks = HID_F + (N_NODES + 255) / 256;     // prep + init

    // init + weight prep (fused), degree, norm
    k_initprep<<<init_blocks, 256>>>(W1, W2);
    k_degree  <<<(N_EDGES + 255) / 256, 256>>>(ei);
    k_dinv    <<<(N_NODES + 255) / 256, 256>>>();

    // conv1: H1 = x@W1 (tensor, fp16); A1 = H1*dinv^2 + b1 (fused); edges accumulate
    k_tgemm<IN_F, false, false><<<gemm_blocks, 256, TG_SMEM>>>(
        x, Wt1h, Wt1l, H1, A1, b1, batch, N_NODES);
    k_edge<<<edge_blocks, 256>>>(H1, A1, ei);

    // root-feature GEMM (factored second half of W2)
    k_rootgemm<<<N_GRAPHS, 128>>>(x, root, W2);

    // conv2: H2 = relu(A1)@W2a + R[batch] (fp16); O = H2*dinv^2 + b2; edges accumulate
    k_tgemm<HID_F, true, true><<<gemm_blocks, 256, TG_SMEM>>>(
        A1, Wt2h, Wt2l, H2, O, b2, batch, N_NODES);
    k_edge<<<edge_blocks, 256>>>(H2, O, ei);

    // graph mean + output
    k_reduce<<<(N_NODES + NPB - 1) / NPB, 128>>>(batch);
    k_final <<<N_GRAPHS, 256>>>(root, out);
}

// round 15
// speedup vs baseline: 1.0098x; 1.0098x over previous
#include <cuda_runtime.h>
#include <cuda_bf16.h>
#include <cuda_fp16.h>
#include <cstdint>

#define N_NODES  200000
#define N_EDGES  200000
#define N_GRAPHS 128
#define IN_F     256
#define HID_F    128
#define OUT_F    128

// ---------------- scratch (static device globals; no allocation) -------------
__device__ __half g_H1[(size_t)N_NODES * HID_F];  // x @ W1            (fp16)
__device__ float  g_A1[(size_t)N_NODES * HID_F];  // conv1 output (x2)
__device__ __half g_H2[(size_t)N_NODES * HID_F];  // relu(A1)@W2a + R  (fp16)
__device__ float  g_O [(size_t)N_NODES * HID_F];  // conv2 pre-relu
__device__ float g_deg [N_NODES];
__device__ float g_dinv[N_NODES];
__device__ float g_R   [N_GRAPHS * HID_F];        // relu(x[root]) @ W2[128:384]
__device__ float g_gsum[N_GRAPHS * HID_F];
__device__ float g_gcnt[N_GRAPHS];
// transposed fp16 hi/lo weights: Wt[n*K + k]  (2-term split: B = Bh + Bl)
__device__ __half g_Wt1h[HID_F * IN_F];
__device__ __half g_Wt1l[HID_F * IN_F];
__device__ __half g_Wt2h[HID_F * HID_F];
__device__ __half g_Wt2l[HID_F * HID_F];

// ---------------- helpers -----------------------------------------------------
__device__ __forceinline__ void mma_f16(float* c, const uint32_t* a, const uint32_t* b) {
    asm volatile(
        "mma.sync.aligned.m16n8k16.row.col.f32.f16.f16.f32 "
        "{%0,%1,%2,%3}, {%4,%5,%6,%7}, {%8,%9}, {%0,%1,%2,%3};"
        : "+f"(c[0]), "+f"(c[1]), "+f"(c[2]), "+f"(c[3])
        : "r"(a[0]), "r"(a[1]), "r"(a[2]), "r"(a[3]), "r"(b[0]), "r"(b[1]));
}

__device__ __forceinline__ void red_v4(float* addr, float a, float b, float c, float d) {
    asm volatile("red.global.add.v4.f32 [%0], {%1, %2, %3, %4};"
        :: "l"(addr), "f"(a), "f"(b), "f"(c), "f"(d) : "memory");
}

__device__ __forceinline__ uint32_t h2bits(__half2 h) {
    return *reinterpret_cast<uint32_t*>(&h);
}

// ---------------- fused init + weight prep ------------------------------------
__global__ void k_initprep(const float* __restrict__ W1, const float* __restrict__ W2) {
    if (blockIdx.x < HID_F) {
        int n = blockIdx.x;      // 0..127
        int k = threadIdx.x;     // 0..255
        float v = W1[(size_t)k * HID_F + n];
        __half h = __float2half_rn(v);
        g_Wt1h[n * IN_F + k] = h;
        g_Wt1l[n * IN_F + k] = __float2half_rn(v - __half2float(h));
        if (k < HID_F) {
            float v2 = W2[(size_t)k * OUT_F + n];
            __half h2 = __float2half_rn(v2);
            g_Wt2h[n * HID_F + k] = h2;
            g_Wt2l[n * HID_F + k] = __float2half_rn(v2 - __half2float(h2));
        }
    } else {
        int i = (blockIdx.x - HID_F) * blockDim.x + threadIdx.x;
        if (i < N_NODES) g_deg[i] = 1.0f;           // self-loop
        if (i < N_GRAPHS * HID_F) g_gsum[i] = 0.0f;
        if (i < N_GRAPHS) g_gcnt[i] = 0.0f;
    }
}

__global__ void k_degree(const int* __restrict__ ei) {
    int e = blockIdx.x * blockDim.x + threadIdx.x;
    if (e >= N_EDGES) return;
    atomicAdd(&g_deg[ei[N_EDGES + e]], 1.0f);
}

__global__ void k_dinv(void) {
    int i = blockIdx.x * blockDim.x + threadIdx.x;
    if (i >= N_NODES) return;
    g_dinv[i] = rsqrtf(g_deg[i]);
}

// one warp per edge: D[dst] += H[src] * dinv[src]*dinv[dst]   (fp16 gather, v4 RED)
__global__ void k_edge(const __half* __restrict__ H, float* __restrict__ D,
                       const int* __restrict__ ei) {
    int e = blockIdx.x * (blockDim.x >> 5) + (threadIdx.x >> 5);
    if (e >= N_EDGES) return;
    int lane = threadIdx.x & 31;
    int s = ei[e], d = ei[N_EDGES + e];
    float c = g_dinv[s] * g_dinv[d];
    uint2 raw = *(const uint2*)(H + (size_t)s * HID_F + lane * 4);
    __half2 h0 = *reinterpret_cast<__half2*>(&raw.x);
    __half2 h1 = *reinterpret_cast<__half2*>(&raw.y);
    float2 f0 = __half22float2(h0);
    float2 f1 = __half22float2(h1);
    float* o = D + (size_t)d * HID_F + lane * 4;
    red_v4(o, f0.x * c, f0.y * c, f1.x * c, f1.y * c);
}

// R[g] = relu(x[root[g]]) @ W2[128:384]
__global__ void k_rootgemm(const float* __restrict__ x,
                           const int* __restrict__ root,
                           const float* __restrict__ W2) {
    __shared__ float xr[IN_F];
    int g = blockIdx.x, t = threadIdx.x;
    int r = root[g];
    xr[t]       = fmaxf(x[(size_t)r * IN_F + t], 0.0f);
    xr[t + 128] = fmaxf(x[(size_t)r * IN_F + t + 128], 0.0f);
    __syncthreads();
    float acc = 0.0f;
#pragma unroll 8
    for (int k = 0; k < IN_F; k++)
        acc += xr[k] * W2[(size_t)(HID_F + k) * OUT_F + t];
    g_R[g * HID_F + t] = acc;
}

// ---------------- tensor-core GEMM: C[M,128] = op(A[M,K]) @ Wt^T --------------
// mma.sync m16n8k16 fp16, 2-term split (A*Bh + A*Bl), fp32 accum.
// BK=64: half the barriers of BK=32, 8-deep LDG.128 bursts (2x MLP per phase).
// Fused epilogue: H(fp16) = C (+ R[batch]);  D(fp32) = C * dinv^2 + bias.
#define BK   64
#define SAPD 72      // smem stride in halves (64 + pad 8)

template<int K, bool RELU_A, bool ADD_R>
__global__ __launch_bounds__(256, 2)
void k_tgemm(const float* __restrict__ A,
             const __half* __restrict__ Bh,
             const __half* __restrict__ Bl,
             __half* __restrict__ H, float* __restrict__ D,
             const float* __restrict__ bias,
             const int* __restrict__ batch, int M) {
    __shared__ uint16_t sA[128 * SAPD];     // fp16 A  [row*SAPD + k]
    __shared__ uint16_t sB[2][128 * SAPD];  // [hi|lo][n*SAPD + k]

    const int tid  = threadIdx.x;
    const int wid  = tid >> 5;
    const int lane = tid & 31;
    const int g8   = lane >> 2;            // 0..7
    const int t2   = (lane & 3) * 2;       // 0,2,4,6
    const int warp_m = (wid >> 2) * 64;    // 0 or 64
    const int warp_n = (wid & 3) * 32;     // 0..96
    const int blockRow = blockIdx.x * 128;

    float acc[4][4][4];
#pragma unroll
    for (int i = 0; i < 4; i++)
#pragma unroll
        for (int j = 0; j < 4; j++)
#pragma unroll
            for (int q = 0; q < 4; q++) acc[i][j][q] = 0.0f;

    for (int k0 = 0; k0 < K; k0 += BK) {
        __syncthreads();
        // ---- A tile: 128 x 64 fp32 -> fp16 (2048 float4 slots, 8/thread) ----
#pragma unroll
        for (int it = 0; it < 8; it++) {
            int linear = tid + it * 256;
            int row = linear >> 4;            // 16 float4 per row
            int c4  = (linear & 15) * 4;
            int gr = blockRow + row;
            float4 v = make_float4(0.f, 0.f, 0.f, 0.f);
            if (gr < M) v = *(const float4*)(A + (size_t)gr * K + k0 + c4);
            if (RELU_A) {
                v.x = fmaxf(v.x, 0.f); v.y = fmaxf(v.y, 0.f);
                v.z = fmaxf(v.z, 0.f); v.w = fmaxf(v.w, 0.f);
            }
            __half2 p0 = __floats2half2_rn(v.x, v.y);
            __half2 p1 = __floats2half2_rn(v.z, v.w);
            int ho = row * SAPD + c4;
            *(uint32_t*)&sA[ho]     = h2bits(p0);
            *(uint32_t*)&sA[ho + 2] = h2bits(p1);
        }
        // ---- B tiles: 128 n x 64 k fp16 (1024 uint4 lines per term) ----
#pragma unroll
        for (int it = 0; it < 4; it++) {
            int linear = tid + it * 256;
            int n  = linear >> 3;             // 8 lines per row
            int k8 = (linear & 7) * 8;
            size_t gi = ((size_t)n * K + k0 + k8) / 8;   // uint4 index
            int ho = n * SAPD + k8;
            *(uint4*)&sB[0][ho] = ((const uint4*)Bh)[gi];
            *(uint4*)&sB[1][ho] = ((const uint4*)Bl)[gi];
        }
        __syncthreads();

        // ---- compute: 4 k16-steps x 2 split terms x (4m x 4n) mma ----
#pragma unroll
        for (int ks = 0; ks < 4; ks++) {
            const int kk = ks * 16;
            uint32_t ah[4][4], bh[4][2], bl[4][2];
#pragma unroll
            for (int mt = 0; mt < 4; mt++) {
                int r = warp_m + mt * 16 + g8;
                int ho = r * SAPD + kk + t2;
                ah[mt][0] = *(const uint32_t*)&sA[ho];
                ah[mt][1] = *(const uint32_t*)&sA[ho + 8 * SAPD];
                ah[mt][2] = *(const uint32_t*)&sA[ho + 8];
                ah[mt][3] = *(const uint32_t*)&sA[ho + 8 * SAPD + 8];
            }
#pragma unroll
            for (int nt = 0; nt < 4; nt++) {
                int n = warp_n + nt * 8 + g8;
                int ho = n * SAPD + kk + t2;
                bh[nt][0] = *(const uint32_t*)&sB[0][ho];
                bh[nt][1] = *(const uint32_t*)&sB[0][ho + 8];
                bl[nt][0] = *(const uint32_t*)&sB[1][ho];
                bl[nt][1] = *(const uint32_t*)&sB[1][ho + 8];
            }
#pragma unroll
            for (int mt = 0; mt < 4; mt++)
#pragma unroll
                for (int nt = 0; nt < 4; nt++) {
                    mma_f16(acc[mt][nt], ah[mt], bh[nt]);
                    mma_f16(acc[mt][nt], ah[mt], bl[nt]);
                }
        }
    }

    // ---- epilogue: H(fp16) = acc (+R[batch]);  D = H*dinv^2 + bias ----
#pragma unroll
    for (int mt = 0; mt < 4; mt++) {
#pragma unroll
        for (int half = 0; half < 2; half++) {
            int row = blockRow + warp_m + mt * 16 + g8 + half * 8;
            if (row >= M) continue;
            float dv = g_dinv[row];
            float ds = dv * dv;
            const float* Rrow = ADD_R ? (g_R + (size_t)batch[row] * HID_F) : nullptr;
#pragma unroll
            for (int nt = 0; nt < 4; nt++) {
                int col = warp_n + nt * 8 + t2;
                float v0 = acc[mt][nt][half * 2 + 0];
                float v1 = acc[mt][nt][half * 2 + 1];
                if (ADD_R) { v0 += Rrow[col]; v1 += Rrow[col + 1]; }
                *(__half2*)(H + (size_t)row * HID_F + col) = __floats2half2_rn(v0, v1);
                float b0 = bias[col], b1 = bias[col + 1];
                *(float2*)(D + (size_t)row * HID_F + col) =
                    make_float2(v0 * ds + b0, v1 * ds + b1);
            }
        }
    }
}

// ---------------- graph mean reduction (batch is sorted) ----------------------
#define NPB 128
__global__ void k_reduce(const int* __restrict__ batch) {
    int c = threadIdx.x;                      // 0..127 (column)
    int start = blockIdx.x * NPB;
    if (start >= N_NODES) return;
    int end = min(start + NPB, N_NODES);
    int curg = batch[start];
    float acc = 0.0f; int cnt = 0;
    for (int i = start; i < end; i++) {
        int g = batch[i];
        if (g != curg) {
            atomicAdd(&g_gsum[curg * HID_F + c], acc);
            if (c == 0) atomicAdd(&g_gcnt[curg], (float)cnt);
            acc = 0.0f; cnt = 0; curg = g;
        }
        acc += fmaxf(g_O[(size_t)i * HID_F + c], 0.0f);
        cnt++;
    }
    atomicAdd(&g_gsum[curg * HID_F + c], acc);
    if (c == 0) atomicAdd(&g_gcnt[curg], (float)cnt);
}

__global__ void k_final(const int* __restrict__ root, float* __restrict__ out) {
    int g = blockIdx.x, c = threadIdx.x;      // 256 threads
    float cnt = g_gcnt[g];
    float v;
    if (c < HID_F) {
        v = g_gsum[g * HID_F + c] / fmaxf(cnt, 1.0f);
    } else {
        v = (cnt > 0.0f) ? g_A1[(size_t)root[g] * HID_F + (c - HID_F)] : 0.0f;
    }
    out[g * 256 + c] = v;
}

// ---------------- launch ------------------------------------------------------
extern "C" void kernel_launch(void* const* d_in, const int* in_sizes, int n_in,
                              void* d_out, int out_size) {
    const float* x     = (const float*)d_in[0];
    const int*   ei    = (const int*)  d_in[1];
    const int*   batch = (const int*)  d_in[2];
    const int*   root  = (const int*)  d_in[3];
    const float* W1    = (const float*)d_in[4];
    const float* b1    = (const float*)d_in[5];
    const float* W2    = (const float*)d_in[6];
    const float* b2    = (const float*)d_in[7];
    float* out = (float*)d_out;

    float *A1, *O;
    __half *H1, *H2;
    __half *Wt1h, *Wt1l, *Wt2h, *Wt2l;
    cudaGetSymbolAddress((void**)&H1, g_H1);
    cudaGetSymbolAddress((void**)&A1, g_A1);
    cudaGetSymbolAddress((void**)&H2, g_H2);
    cudaGetSymbolAddress((void**)&O,  g_O);
    cudaGetSymbolAddress((void**)&Wt1h, g_Wt1h);
    cudaGetSymbolAddress((void**)&Wt1l, g_Wt1l);
    cudaGetSymbolAddress((void**)&Wt2h, g_Wt2h);
    cudaGetSymbolAddress((void**)&Wt2l, g_Wt2l);

    const int gemm_blocks = (N_NODES + 127) / 128;             // 1563
    const int edge_blocks = (N_EDGES + 7) / 8;                 // 8 edges/block @256thr
    const int init_blocks = HID_F + (N_NODES + 255) / 256;     // prep + init

    // init + weight prep (fused), degree, norm
    k_initprep<<<init_blocks, 256>>>(W1, W2);
    k_degree  <<<(N_EDGES + 255) / 256, 256>>>(ei);
    k_dinv    <<<(N_NODES + 255) / 256, 256>>>();

    // conv1: H1 = x@W1 (tensor, fp16); A1 = H1*dinv^2 + b1 (fused); edges accumulate
    k_tgemm<IN_F, false, false><<<gemm_blocks, 256>>>(
        x, Wt1h, Wt1l, H1, A1, b1, batch, N_NODES);
    k_edge<<<edge_blocks, 256>>>(H1, A1, ei);

    // root-feature GEMM (factored second half of W2)
    k_rootgemm<<<N_GRAPHS, 128>>>(x, root, W2);

    // conv2: H2 = relu(A1)@W2a + R[batch] (fp16); O = H2*dinv^2 + b2; edges accumulate
    k_tgemm<HID_F, true, true><<<gemm_blocks, 256>>>(
        A1, Wt2h, Wt2l, H2, O, b2, batch, N_NODES);
    k_edge<<<edge_blocks, 256>>>(H2, O, ei);

    // graph mean + output
    k_reduce<<<(N_NODES + NPB - 1) / NPB, 128>>>(batch);
    k_final <<<N_GRAPHS, 256>>>(root, out);
}

// round 16
// speedup vs baseline: 1.1699x; 1.1585x over previous
#include <cuda_runtime.h>
#include <cuda_bf16.h>
#include <cuda_fp16.h>
#include <cstdint>

#define N_NODES  200000
#define N_EDGES  200000
#define N_GRAPHS 128
#define IN_F     256
#define HID_F    128
#define OUT_F    128

// ---------------- scratch (static device globals; no allocation) -------------
__device__ __half g_H1[(size_t)N_NODES * HID_F];  // x @ W1              (fp16)
__device__ __half g_A1[(size_t)N_NODES * HID_F];  // conv1 output (x2)   (fp16)
__device__ __half g_H2[(size_t)N_NODES * HID_F];  // relu(A1)@W2a + R    (fp16)
__device__ __half g_O [(size_t)N_NODES * HID_F];  // conv2 pre-relu      (fp16)
__device__ float g_deg [N_NODES];
__device__ float g_dinv[N_NODES];
__device__ float g_R   [N_GRAPHS * HID_F];        // relu(x[root]) @ W2[128:384]
__device__ float g_gsum[N_GRAPHS * HID_F];
__device__ float g_gcnt[N_GRAPHS];
// transposed fp16 hi/lo weights: Wt[n*K + k]  (2-term split: B = Bh + Bl)
__device__ __half g_Wt1h[HID_F * IN_F];
__device__ __half g_Wt1l[HID_F * IN_F];
__device__ __half g_Wt2h[HID_F * HID_F];
__device__ __half g_Wt2l[HID_F * HID_F];

// ---------------- helpers -----------------------------------------------------
__device__ __forceinline__ void mma_f16(float* c, const uint32_t* a, const uint32_t* b) {
    asm volatile(
        "mma.sync.aligned.m16n8k16.row.col.f32.f16.f16.f32 "
        "{%0,%1,%2,%3}, {%4,%5,%6,%7}, {%8,%9}, {%0,%1,%2,%3};"
        : "+f"(c[0]), "+f"(c[1]), "+f"(c[2]), "+f"(c[3])
        : "r"(a[0]), "r"(a[1]), "r"(a[2]), "r"(a[3]), "r"(b[0]), "r"(b[1]));
}

__device__ __forceinline__ uint32_t h2bits(__half2 h) {
    return *reinterpret_cast<uint32_t*>(&h);
}

// ---------------- fused init + weight prep ------------------------------------
__global__ void k_initprep(const float* __restrict__ W1, const float* __restrict__ W2) {
    if (blockIdx.x < HID_F) {
        int n = blockIdx.x;      // 0..127
        int k = threadIdx.x;     // 0..255
        float v = W1[(size_t)k * HID_F + n];
        __half h = __float2half_rn(v);
        g_Wt1h[n * IN_F + k] = h;
        g_Wt1l[n * IN_F + k] = __float2half_rn(v - __half2float(h));
        if (k < HID_F) {
            float v2 = W2[(size_t)k * OUT_F + n];
            __half h2 = __float2half_rn(v2);
            g_Wt2h[n * HID_F + k] = h2;
            g_Wt2l[n * HID_F + k] = __float2half_rn(v2 - __half2float(h2));
        }
    } else {
        int i = (blockIdx.x - HID_F) * blockDim.x + threadIdx.x;
        if (i < N_NODES) g_deg[i] = 1.0f;           // self-loop
        if (i < N_GRAPHS * HID_F) g_gsum[i] = 0.0f;
        if (i < N_GRAPHS) g_gcnt[i] = 0.0f;
    }
}

__global__ void k_degree(const int* __restrict__ ei) {
    int e = blockIdx.x * blockDim.x + threadIdx.x;
    if (e >= N_EDGES) return;
    atomicAdd(&g_deg[ei[N_EDGES + e]], 1.0f);
}

__global__ void k_dinv(void) {
    int i = blockIdx.x * blockDim.x + threadIdx.x;
    if (i >= N_NODES) return;
    g_dinv[i] = rsqrtf(g_deg[i]);
}

// half-warp (16 lanes) per edge: D[dst] += H[src] * dinv[s]*dinv[d]
// fp16 gather (uint4 = 8 halves/lane), packed v4.f16x2 reduction (16 REDs/edge).
__global__ void k_edge(const __half* __restrict__ H, __half* __restrict__ D,
                       const int* __restrict__ ei) {
    int warp = blockIdx.x * (blockDim.x >> 5) + (threadIdx.x >> 5);
    int lg   = (threadIdx.x >> 4) & 1;        // half-warp id
    int sub  = threadIdx.x & 15;              // lane within half-warp
    int e = warp * 2 + lg;
    if (e >= N_EDGES) return;
    int s = ei[e], d = ei[N_EDGES + e];
    float c = g_dinv[s] * g_dinv[d];
    __half2 c2 = __float2half2_rn(c);
    uint4 raw = *(const uint4*)(H + (size_t)s * HID_F + sub * 8);
    __half2* hp = reinterpret_cast<__half2*>(&raw);
    uint32_t r0 = h2bits(__hmul2(hp[0], c2));
    uint32_t r1 = h2bits(__hmul2(hp[1], c2));
    uint32_t r2 = h2bits(__hmul2(hp[2], c2));
    uint32_t r3 = h2bits(__hmul2(hp[3], c2));
    __half* o = D + (size_t)d * HID_F + sub * 8;
    asm volatile("red.global.add.noftz.v4.f16x2 [%0], {%1, %2, %3, %4};"
        :: "l"(o), "r"(r0), "r"(r1), "r"(r2), "r"(r3) : "memory");
}

// R[g] = relu(x[root[g]]) @ W2[128:384]
__global__ void k_rootgemm(const float* __restrict__ x,
                           const int* __restrict__ root,
                           const float* __restrict__ W2) {
    __shared__ float xr[IN_F];
    int g = blockIdx.x, t = threadIdx.x;
    int r = root[g];
    xr[t]       = fmaxf(x[(size_t)r * IN_F + t], 0.0f);
    xr[t + 128] = fmaxf(x[(size_t)r * IN_F + t + 128], 0.0f);
    __syncthreads();
    float acc = 0.0f;
#pragma unroll 8
    for (int k = 0; k < IN_F; k++)
        acc += xr[k] * W2[(size_t)(HID_F + k) * OUT_F + t];
    g_R[g * HID_F + t] = acc;
}

// ---------------- tensor-core GEMM: C[M,128] = op(A[M,K]) @ Wt^T --------------
// mma.sync m16n8k16 fp16, 2-term split (A*Bh + A*Bl), fp32 accum.
// A path templated: fp32 (GEMM1, converted in load) or fp16 (GEMM2, direct).
// Fused epilogue: H(fp16) = C (+ R[batch]);  D(fp16) = C * dinv^2 + bias.
#define BK   64
#define SAPD 72      // smem stride in halves (64 + pad 8)

template<int K, bool A_HALF, bool RELU_A, bool ADD_R>
__global__ __launch_bounds__(256, 2)
void k_tgemm(const void* __restrict__ Av,
             const __half* __restrict__ Bh,
             const __half* __restrict__ Bl,
             __half* __restrict__ H, __half* __restrict__ D,
             const float* __restrict__ bias,
             const int* __restrict__ batch, int M) {
    __shared__ uint16_t sA[128 * SAPD];     // fp16 A  [row*SAPD + k]
    __shared__ uint16_t sB[2][128 * SAPD];  // [hi|lo][n*SAPD + k]

    const int tid  = threadIdx.x;
    const int wid  = tid >> 5;
    const int lane = tid & 31;
    const int g8   = lane >> 2;            // 0..7
    const int t2   = (lane & 3) * 2;       // 0,2,4,6
    const int warp_m = (wid >> 2) * 64;    // 0 or 64
    const int warp_n = (wid & 3) * 32;     // 0..96
    const int blockRow = blockIdx.x * 128;

    float acc[4][4][4];
#pragma unroll
    for (int i = 0; i < 4; i++)
#pragma unroll
        for (int j = 0; j < 4; j++)
#pragma unroll
            for (int q = 0; q < 4; q++) acc[i][j][q] = 0.0f;

    for (int k0 = 0; k0 < K; k0 += BK) {
        __syncthreads();
        if (!A_HALF) {
            // ---- A tile: 128 x 64 fp32 -> fp16 (2048 float4 slots) ----
            const float* A = (const float*)Av;
#pragma unroll
            for (int it = 0; it < 8; it++) {
                int linear = tid + it * 256;
                int row = linear >> 4;            // 16 float4 per row
                int c4  = (linear & 15) * 4;
                int gr = blockRow + row;
                float4 v = make_float4(0.f, 0.f, 0.f, 0.f);
                if (gr < M) v = *(const float4*)(A + (size_t)gr * K + k0 + c4);
                if (RELU_A) {
                    v.x = fmaxf(v.x, 0.f); v.y = fmaxf(v.y, 0.f);
                    v.z = fmaxf(v.z, 0.f); v.w = fmaxf(v.w, 0.f);
                }
                __half2 p0 = __floats2half2_rn(v.x, v.y);
                __half2 p1 = __floats2half2_rn(v.z, v.w);
                int ho = row * SAPD + c4;
                *(uint32_t*)&sA[ho]     = h2bits(p0);
                *(uint32_t*)&sA[ho + 2] = h2bits(p1);
            }
        } else {
            // ---- A tile: 128 x 64 fp16 direct (1024 uint4 lines) ----
            const __half* A = (const __half*)Av;
            const __half2 z2 = __float2half2_rn(0.f);
#pragma unroll
            for (int it = 0; it < 4; it++) {
                int linear = tid + it * 256;
                int row = linear >> 3;            // 8 uint4 per row
                int l8  = (linear & 7) * 8;
                int gr = blockRow + row;
                uint4 v = make_uint4(0u, 0u, 0u, 0u);
                if (gr < M) v = *(const uint4*)(A + (size_t)gr * K + k0 + l8);
                if (RELU_A) {
                    __half2* hp = reinterpret_cast<__half2*>(&v);
                    hp[0] = __hmax2(hp[0], z2);
                    hp[1] = __hmax2(hp[1], z2);
                    hp[2] = __hmax2(hp[2], z2);
                    hp[3] = __hmax2(hp[3], z2);
                }
                *(uint4*)&sA[row * SAPD + l8] = v;
            }
        }
        // ---- B tiles: 128 n x 64 k fp16 (1024 uint4 lines per term) ----
#pragma unroll
        for (int it = 0; it < 4; it++) {
            int linear = tid + it * 256;
            int n  = linear >> 3;             // 8 lines per row
            int k8 = (linear & 7) * 8;
            size_t gi = ((size_t)n * K + k0 + k8) / 8;   // uint4 index
            int ho = n * SAPD + k8;
            *(uint4*)&sB[0][ho] = ((const uint4*)Bh)[gi];
            *(uint4*)&sB[1][ho] = ((const uint4*)Bl)[gi];
        }
        __syncthreads();

        // ---- compute: 4 k16-steps x 2 split terms x (4m x 4n) mma ----
#pragma unroll
        for (int ks = 0; ks < 4; ks++) {
            const int kk = ks * 16;
            uint32_t ah[4][4], bh[4][2], bl[4][2];
#pragma unroll
            for (int mt = 0; mt < 4; mt++) {
                int r = warp_m + mt * 16 + g8;
                int ho = r * SAPD + kk + t2;
                ah[mt][0] = *(const uint32_t*)&sA[ho];
                ah[mt][1] = *(const uint32_t*)&sA[ho + 8 * SAPD];
                ah[mt][2] = *(const uint32_t*)&sA[ho + 8];
                ah[mt][3] = *(const uint32_t*)&sA[ho + 8 * SAPD + 8];
            }
#pragma unroll
            for (int nt = 0; nt < 4; nt++) {
                int n = warp_n + nt * 8 + g8;
                int ho = n * SAPD + kk + t2;
                bh[nt][0] = *(const uint32_t*)&sB[0][ho];
                bh[nt][1] = *(const uint32_t*)&sB[0][ho + 8];
                bl[nt][0] = *(const uint32_t*)&sB[1][ho];
                bl[nt][1] = *(const uint32_t*)&sB[1][ho + 8];
            }
#pragma unroll
            for (int mt = 0; mt < 4; mt++)
#pragma unroll
                for (int nt = 0; nt < 4; nt++) {
                    mma_f16(acc[mt][nt], ah[mt], bh[nt]);
                    mma_f16(acc[mt][nt], ah[mt], bl[nt]);
                }
        }
    }

    // ---- epilogue: H(fp16) = acc (+R[batch]);  D(fp16) = acc*dinv^2 + bias ----
#pragma unroll
    for (int mt = 0; mt < 4; mt++) {
#pragma unroll
        for (int half = 0; half < 2; half++) {
            int row = blockRow + warp_m + mt * 16 + g8 + half * 8;
            if (row >= M) continue;
            float dv = g_dinv[row];
            float ds = dv * dv;
            const float* Rrow = ADD_R ? (g_R + (size_t)batch[row] * HID_F) : nullptr;
#pragma unroll
            for (int nt = 0; nt < 4; nt++) {
                int col = warp_n + nt * 8 + t2;
                float v0 = acc[mt][nt][half * 2 + 0];
                float v1 = acc[mt][nt][half * 2 + 1];
                if (ADD_R) { v0 += Rrow[col]; v1 += Rrow[col + 1]; }
                *(__half2*)(H + (size_t)row * HID_F + col) = __floats2half2_rn(v0, v1);
                float b0 = bias[col], b1 = bias[col + 1];
                *(__half2*)(D + (size_t)row * HID_F + col) =
                    __floats2half2_rn(v0 * ds + b0, v1 * ds + b1);
            }
        }
    }
}

// ---------------- graph mean reduction (batch is sorted, O is fp16) ------------
#define NPB 128
__global__ void k_reduce(const int* __restrict__ batch) {
    int c = threadIdx.x;                      // 0..127 (column)
    int start = blockIdx.x * NPB;
    if (start >= N_NODES) return;
    int end = min(start + NPB, N_NODES);
    int curg = batch[start];
    float acc = 0.0f; int cnt = 0;
    for (int i = start; i < end; i++) {
        int g = batch[i];
        if (g != curg) {
            atomicAdd(&g_gsum[curg * HID_F + c], acc);
            if (c == 0) atomicAdd(&g_gcnt[curg], (float)cnt);
            acc = 0.0f; cnt = 0; curg = g;
        }
        acc += fmaxf(__half2float(g_O[(size_t)i * HID_F + c]), 0.0f);
        cnt++;
    }
    atomicAdd(&g_gsum[curg * HID_F + c], acc);
    if (c == 0) atomicAdd(&g_gcnt[curg], (float)cnt);
}

__global__ void k_final(const int* __restrict__ root, float* __restrict__ out) {
    int g = blockIdx.x, c = threadIdx.x;      // 256 threads
    float cnt = g_gcnt[g];
    float v;
    if (c < HID_F) {
        v = g_gsum[g * HID_F + c] / fmaxf(cnt, 1.0f);
    } else {
        v = (cnt > 0.0f) ? __half2float(g_A1[(size_t)root[g] * HID_F + (c - HID_F)])
                         : 0.0f;
    }
    out[g * 256 + c] = v;
}

// ---------------- launch ------------------------------------------------------
extern "C" void kernel_launch(void* const* d_in, const int* in_sizes, int n_in,
                              void* d_out, int out_size) {
    const float* x     = (const float*)d_in[0];
    const int*   ei    = (const int*)  d_in[1];
    const int*   batch = (const int*)  d_in[2];
    const int*   root  = (const int*)  d_in[3];
    const float* W1    = (const float*)d_in[4];
    const float* b1    = (const float*)d_in[5];
    const float* W2    = (const float*)d_in[6];
    const float* b2    = (const float*)d_in[7];
    float* out = (float*)d_out;

    __half *H1, *A1, *H2, *O;
    __half *Wt1h, *Wt1l, *Wt2h, *Wt2l;
    cudaGetSymbolAddress((void**)&H1, g_H1);
    cudaGetSymbolAddress((void**)&A1, g_A1);
    cudaGetSymbolAddress((void**)&H2, g_H2);
    cudaGetSymbolAddress((void**)&O,  g_O);
    cudaGetSymbolAddress((void**)&Wt1h, g_Wt1h);
    cudaGetSymbolAddress((void**)&Wt1l, g_Wt1l);
    cudaGetSymbolAddress((void**)&Wt2h, g_Wt2h);
    cudaGetSymbolAddress((void**)&Wt2l, g_Wt2l);

    const int gemm_blocks = (N_NODES + 127) / 128;             // 1563
    const int edge_blocks = (N_EDGES + 15) / 16;               // 16 edges/block @256thr
    const int init_blocks = HID_F + (N_NODES + 255) / 256;     // prep + init

    // init + weight prep (fused), degree, norm
    k_initprep<<<init_blocks, 256>>>(W1, W2);
    k_degree  <<<(N_EDGES + 255) / 256, 256>>>(ei);
    k_dinv    <<<(N_NODES + 255) / 256, 256>>>();

    // conv1: H1 = x@W1 (tensor, fp16); A1 = H1*dinv^2 + b1 (fused); edges accumulate
    k_tgemm<IN_F, false, false, false><<<gemm_blocks, 256>>>(
        x, Wt1h, Wt1l, H1, A1, b1, batch, N_NODES);
    k_edge<<<edge_blocks, 256>>>(H1, A1, ei);

    // root-feature GEMM (factored second half of W2)
    k_rootgemm<<<N_GRAPHS, 128>>>(x, root, W2);

    // conv2: H2 = relu(A1)@W2a + R[batch] (fp16); O = H2*dinv^2 + b2; edges accumulate
    k_tgemm<HID_F, true, true, true><<<gemm_blocks, 256>>>(
        A1, Wt2h, Wt2l, H2, O, b2, batch, N_NODES);
    k_edge<<<edge_blocks, 256>>>(H2, O, ei);

    // graph mean + output
    k_reduce<<<(N_NODES + NPB - 1) / NPB, 128>>>(batch);
    k_final <<<N_GRAPHS, 256>>>(root, out);
}

// round 17
// speedup vs baseline: 1.3566x; 1.1596x over previous
#include <cuda_runtime.h>
#include <cuda_bf16.h>
#include <cuda_fp16.h>
#include <cstdint>

#define N_NODES  200000
#define N_EDGES  200000
#define N_GRAPHS 128
#define IN_F     256
#define HID_F    128
#define OUT_F    128

// ---------------- scratch (static device globals; no allocation) -------------
__device__ __half g_H1[(size_t)N_NODES * HID_F];  // x @ W1              (fp16)
__device__ __half g_A1[(size_t)N_NODES * HID_F];  // conv1 output (x2)   (fp16)
__device__ __half g_H2[(size_t)N_NODES * HID_F];  // relu(A1)@W2a + R    (fp16)
__device__ __half g_O [(size_t)N_NODES * HID_F];  // conv2 pre-relu      (fp16)
__device__ float g_deg [N_NODES];
__device__ float g_dinv[N_NODES];
__device__ float g_R   [N_GRAPHS * HID_F];        // relu(x[root]) @ W2[128:384]
__device__ float g_gsum[N_GRAPHS * HID_F];
__device__ float g_gcnt[N_GRAPHS];
// transposed fp16 weights: Wt[n*K + k]  (single term)
__device__ __half g_Wt1[HID_F * IN_F];
__device__ __half g_Wt2[HID_F * HID_F];

// ---------------- helpers -----------------------------------------------------
__device__ __forceinline__ void mma_f16(float* c, const uint32_t* a, const uint32_t* b) {
    asm volatile(
        "mma.sync.aligned.m16n8k16.row.col.f32.f16.f16.f32 "
        "{%0,%1,%2,%3}, {%4,%5,%6,%7}, {%8,%9}, {%0,%1,%2,%3};"
        : "+f"(c[0]), "+f"(c[1]), "+f"(c[2]), "+f"(c[3])
        : "r"(a[0]), "r"(a[1]), "r"(a[2]), "r"(a[3]), "r"(b[0]), "r"(b[1]));
}

__device__ __forceinline__ uint32_t h2bits(__half2 h) {
    return *reinterpret_cast<uint32_t*>(&h);
}

// ---------------- fused init + weight prep ------------------------------------
__global__ void k_initprep(const float* __restrict__ W1, const float* __restrict__ W2) {
    if (blockIdx.x < HID_F) {
        int n = blockIdx.x;      // 0..127
        int k = threadIdx.x;     // 0..255
        g_Wt1[n * IN_F + k] = __float2half_rn(W1[(size_t)k * HID_F + n]);
        if (k < HID_F)
            g_Wt2[n * HID_F + k] = __float2half_rn(W2[(size_t)k * OUT_F + n]);
    } else {
        int i = (blockIdx.x - HID_F) * blockDim.x + threadIdx.x;
        if (i < N_NODES) g_deg[i] = 1.0f;           // self-loop
        if (i < N_GRAPHS * HID_F) g_gsum[i] = 0.0f;
        if (i < N_GRAPHS) g_gcnt[i] = 0.0f;
    }
}

__global__ void k_degree(const int* __restrict__ ei) {
    int e = blockIdx.x * blockDim.x + threadIdx.x;
    if (e >= N_EDGES) return;
    atomicAdd(&g_deg[ei[N_EDGES + e]], 1.0f);
}

__global__ void k_dinv(void) {
    int i = blockIdx.x * blockDim.x + threadIdx.x;
    if (i >= N_NODES) return;
    g_dinv[i] = rsqrtf(g_deg[i]);
}

// half-warp (16 lanes) per edge: D[dst] += H[src] * dinv[s]*dinv[d]
// fp16 gather (uint4 = 8 halves/lane), packed v4.f16x2 reduction (16 REDs/edge).
__global__ void k_edge(const __half* __restrict__ H, __half* __restrict__ D,
                       const int* __restrict__ ei) {
    int warp = blockIdx.x * (blockDim.x >> 5) + (threadIdx.x >> 5);
    int lg   = (threadIdx.x >> 4) & 1;        // half-warp id
    int sub  = threadIdx.x & 15;              // lane within half-warp
    int e = warp * 2 + lg;
    if (e >= N_EDGES) return;
    int s = ei[e], d = ei[N_EDGES + e];
    float c = g_dinv[s] * g_dinv[d];
    __half2 c2 = __float2half2_rn(c);
    uint4 raw = *(const uint4*)(H + (size_t)s * HID_F + sub * 8);
    __half2* hp = reinterpret_cast<__half2*>(&raw);
    uint32_t r0 = h2bits(__hmul2(hp[0], c2));
    uint32_t r1 = h2bits(__hmul2(hp[1], c2));
    uint32_t r2 = h2bits(__hmul2(hp[2], c2));
    uint32_t r3 = h2bits(__hmul2(hp[3], c2));
    __half* o = D + (size_t)d * HID_F + sub * 8;
    asm volatile("red.global.add.noftz.v4.f16x2 [%0], {%1, %2, %3, %4};"
        :: "l"(o), "r"(r0), "r"(r1), "r"(r2), "r"(r3) : "memory");
}

// R[g] = relu(x[root[g]]) @ W2[128:384]
__global__ void k_rootgemm(const float* __restrict__ x,
                           const int* __restrict__ root,
                           const float* __restrict__ W2) {
    __shared__ float xr[IN_F];
    int g = blockIdx.x, t = threadIdx.x;
    int r = root[g];
    xr[t]       = fmaxf(x[(size_t)r * IN_F + t], 0.0f);
    xr[t + 128] = fmaxf(x[(size_t)r * IN_F + t + 128], 0.0f);
    __syncthreads();
    float acc = 0.0f;
#pragma unroll 8
    for (int k = 0; k < IN_F; k++)
        acc += xr[k] * W2[(size_t)(HID_F + k) * OUT_F + t];
    g_R[g * HID_F + t] = acc;
}

// ---------------- tensor-core GEMM: C[M,128] = op(A[M,K]) @ Wt^T --------------
// mma.sync m16n8k16 fp16, single-term fp16 weights, fp32 accum.
// A path templated: fp32 (GEMM1, converted in load) or fp16 (GEMM2, direct).
// Fused epilogue: H(fp16) = C (+ R[batch]);  D(fp16) = C * dinv^2 + bias.
#define BK   64
#define SAPD 72      // smem stride in halves (64 + pad 8)

template<int K, bool A_HALF, bool RELU_A, bool ADD_R>
__global__ __launch_bounds__(256, 2)
void k_tgemm(const void* __restrict__ Av,
             const __half* __restrict__ B,
             __half* __restrict__ H, __half* __restrict__ D,
             const float* __restrict__ bias,
             const int* __restrict__ batch, int M) {
    __shared__ uint16_t sA[128 * SAPD];     // fp16 A  [row*SAPD + k]
    __shared__ uint16_t sB[128 * SAPD];     // fp16 B  [n*SAPD + k]

    const int tid  = threadIdx.x;
    const int wid  = tid >> 5;
    const int lane = tid & 31;
    const int g8   = lane >> 2;            // 0..7
    const int t2   = (lane & 3) * 2;       // 0,2,4,6
    const int warp_m = (wid >> 2) * 64;    // 0 or 64
    const int warp_n = (wid & 3) * 32;     // 0..96
    const int blockRow = blockIdx.x * 128;

    float acc[4][4][4];
#pragma unroll
    for (int i = 0; i < 4; i++)
#pragma unroll
        for (int j = 0; j < 4; j++)
#pragma unroll
            for (int q = 0; q < 4; q++) acc[i][j][q] = 0.0f;

    for (int k0 = 0; k0 < K; k0 += BK) {
        __syncthreads();
        if (!A_HALF) {
            // ---- A tile: 128 x 64 fp32 -> fp16 (2048 float4 slots) ----
            const float* A = (const float*)Av;
#pragma unroll
            for (int it = 0; it < 8; it++) {
                int linear = tid + it * 256;
                int row = linear >> 4;            // 16 float4 per row
                int c4  = (linear & 15) * 4;
                int gr = blockRow + row;
                float4 v = make_float4(0.f, 0.f, 0.f, 0.f);
                if (gr < M) v = *(const float4*)(A + (size_t)gr * K + k0 + c4);
                if (RELU_A) {
                    v.x = fmaxf(v.x, 0.f); v.y = fmaxf(v.y, 0.f);
                    v.z = fmaxf(v.z, 0.f); v.w = fmaxf(v.w, 0.f);
                }
                __half2 p0 = __floats2half2_rn(v.x, v.y);
                __half2 p1 = __floats2half2_rn(v.z, v.w);
                int ho = row * SAPD + c4;
                *(uint32_t*)&sA[ho]     = h2bits(p0);
                *(uint32_t*)&sA[ho + 2] = h2bits(p1);
            }
        } else {
            // ---- A tile: 128 x 64 fp16 direct (1024 uint4 lines) ----
            const __half* A = (const __half*)Av;
            const __half2 z2 = __float2half2_rn(0.f);
#pragma unroll
            for (int it = 0; it < 4; it++) {
                int linear = tid + it * 256;
                int row = linear >> 3;            // 8 uint4 per row
                int l8  = (linear & 7) * 8;
                int gr = blockRow + row;
                uint4 v = make_uint4(0u, 0u, 0u, 0u);
                if (gr < M) v = *(const uint4*)(A + (size_t)gr * K + k0 + l8);
                if (RELU_A) {
                    __half2* hp = reinterpret_cast<__half2*>(&v);
                    hp[0] = __hmax2(hp[0], z2);
                    hp[1] = __hmax2(hp[1], z2);
                    hp[2] = __hmax2(hp[2], z2);
                    hp[3] = __hmax2(hp[3], z2);
                }
                *(uint4*)&sA[row * SAPD + l8] = v;
            }
        }
        // ---- B tile: 128 n x 64 k fp16 (1024 uint4 lines) ----
#pragma unroll
        for (int it = 0; it < 4; it++) {
            int linear = tid + it * 256;
            int n  = linear >> 3;             // 8 lines per row
            int k8 = (linear & 7) * 8;
            size_t gi = ((size_t)n * K + k0 + k8) / 8;   // uint4 index
            *(uint4*)&sB[n * SAPD + k8] = ((const uint4*)B)[gi];
        }
        __syncthreads();

        // ---- compute: 4 k16-steps x (4m x 4n) mma ----
#pragma unroll
        for (int ks = 0; ks < 4; ks++) {
            const int kk = ks * 16;
            uint32_t ah[4][4], bf[4][2];
#pragma unroll
            for (int mt = 0; mt < 4; mt++) {
                int r = warp_m + mt * 16 + g8;
                int ho = r * SAPD + kk + t2;
                ah[mt][0] = *(const uint32_t*)&sA[ho];
                ah[mt][1] = *(const uint32_t*)&sA[ho + 8 * SAPD];
                ah[mt][2] = *(const uint32_t*)&sA[ho + 8];
                ah[mt][3] = *(const uint32_t*)&sA[ho + 8 * SAPD + 8];
            }
#pragma unroll
            for (int nt = 0; nt < 4; nt++) {
                int n = warp_n + nt * 8 + g8;
                int ho = n * SAPD + kk + t2;
                bf[nt][0] = *(const uint32_t*)&sB[ho];
                bf[nt][1] = *(const uint32_t*)&sB[ho + 8];
            }
#pragma unroll
            for (int mt = 0; mt < 4; mt++)
#pragma unroll
                for (int nt = 0; nt < 4; nt++)
                    mma_f16(acc[mt][nt], ah[mt], bf[nt]);
        }
    }

    // ---- epilogue: H(fp16) = acc (+R[batch]);  D(fp16) = acc*dinv^2 + bias ----
#pragma unroll
    for (int mt = 0; mt < 4; mt++) {
#pragma unroll
        for (int half = 0; half < 2; half++) {
            int row = blockRow + warp_m + mt * 16 + g8 + half * 8;
            if (row >= M) continue;
            float dv = g_dinv[row];
            float ds = dv * dv;
            const float* Rrow = ADD_R ? (g_R + (size_t)batch[row] * HID_F) : nullptr;
#pragma unroll
            for (int nt = 0; nt < 4; nt++) {
                int col = warp_n + nt * 8 + t2;
                float v0 = acc[mt][nt][half * 2 + 0];
                float v1 = acc[mt][nt][half * 2 + 1];
                if (ADD_R) { v0 += Rrow[col]; v1 += Rrow[col + 1]; }
                *(__half2*)(H + (size_t)row * HID_F + col) = __floats2half2_rn(v0, v1);
                float b0 = bias[col], b1 = bias[col + 1];
                *(__half2*)(D + (size_t)row * HID_F + col) =
                    __floats2half2_rn(v0 * ds + b0, v1 * ds + b1);
            }
        }
    }
}

// ---------------- graph mean reduction (batch is sorted, O is fp16) ------------
#define NPB 128
__global__ void k_reduce(const int* __restrict__ batch) {
    int c = threadIdx.x;                      // 0..127 (column)
    int start = blockIdx.x * NPB;
    if (start >= N_NODES) return;
    int end = min(start + NPB, N_NODES);
    int curg = batch[start];
    float acc = 0.0f; int cnt = 0;
    for (int i = start; i < end; i++) {
        int g = batch[i];
        if (g != curg) {
            atomicAdd(&g_gsum[curg * HID_F + c], acc);
            if (c == 0) atomicAdd(&g_gcnt[curg], (float)cnt);
            acc = 0.0f; cnt = 0; curg = g;
        }
        acc += fmaxf(__half2float(g_O[(size_t)i * HID_F + c]), 0.0f);
        cnt++;
    }
    atomicAdd(&g_gsum[curg * HID_F + c], acc);
    if (c == 0) atomicAdd(&g_gcnt[curg], (float)cnt);
}

__global__ void k_final(const int* __restrict__ root, float* __restrict__ out) {
    int g = blockIdx.x, c = threadIdx.x;      // 256 threads
    float cnt = g_gcnt[g];
    float v;
    if (c < HID_F) {
        v = g_gsum[g * HID_F + c] / fmaxf(cnt, 1.0f);
    } else {
        v = (cnt > 0.0f) ? __half2float(g_A1[(size_t)root[g] * HID_F + (c - HID_F)])
                         : 0.0f;
    }
    out[g * 256 + c] = v;
}

// ---------------- launch ------------------------------------------------------
extern "C" void kernel_launch(void* const* d_in, const int* in_sizes, int n_in,
                              void* d_out, int out_size) {
    const float* x     = (const float*)d_in[0];
    const int*   ei    = (const int*)  d_in[1];
    const int*   batch = (const int*)  d_in[2];
    const int*   root  = (const int*)  d_in[3];
    const float* W1    = (const float*)d_in[4];
    const float* b1    = (const float*)d_in[5];
    const float* W2    = (const float*)d_in[6];
    const float* b2    = (const float*)d_in[7];
    float* out = (float*)d_out;

    __half *H1, *A1, *H2, *O, *Wt1, *Wt2;
    cudaGetSymbolAddress((void**)&H1, g_H1);
    cudaGetSymbolAddress((void**)&A1, g_A1);
    cudaGetSymbolAddress((void**)&H2, g_H2);
    cudaGetSymbolAddress((void**)&O,  g_O);
    cudaGetSymbolAddress((void**)&Wt1, g_Wt1);
    cudaGetSymbolAddress((void**)&Wt2, g_Wt2);

    const int gemm_blocks = (N_NODES + 127) / 128;             // 1563
    const int edge_blocks = (N_EDGES + 15) / 16;               // 16 edges/block @256thr
    const int init_blocks = HID_F + (N_NODES + 255) / 256;     // prep + init

    // init + weight prep (fused), degree, norm
    k_initprep<<<init_blocks, 256>>>(W1, W2);
    k_degree  <<<(N_EDGES + 255) / 256, 256>>>(ei);
    k_dinv    <<<(N_NODES + 255) / 256, 256>>>();

    // conv1: H1 = x@W1 (tensor, fp16); A1 = H1*dinv^2 + b1 (fused); edges accumulate
    k_tgemm<IN_F, false, false, false><<<gemm_blocks, 256>>>(
        x, Wt1, H1, A1, b1, batch, N_NODES);
    k_edge<<<edge_blocks, 256>>>(H1, A1, ei);

    // root-feature GEMM (factored second half of W2)
    k_rootgemm<<<N_GRAPHS, 128>>>(x, root, W2);

    // conv2: H2 = relu(A1)@W2a + R[batch] (fp16); O = H2*dinv^2 + b2; edges accumulate
    k_tgemm<HID_F, true, true, true><<<gemm_blocks, 256>>>(
        A1, Wt2, H2, O, b2, batch, N_NODES);
    k_edge<<<edge_blocks, 256>>>(H2, O, ei);

    // graph mean + output
    k_reduce<<<(N_NODES + NPB - 1) / NPB, 128>>>(batch);
    k_final <<<N_GRAPHS, 256>>>(root, out);
}